// round 15
// baseline (speedup 1.0000x reference)
#include <cuda_runtime.h>
#include <cuda_bf16.h>

// BlockMaskGenerator: B=8192 batches, NUM_BLOCKS=4 rectangles each, 64x64 grid.
// Output buffer is FLOAT32, flattened in reference order:
//   [0,       BS)  context_mask (= !target)       BS = B*4096
//   [BS,     2BS)  target_mask
//   [2BS,    3BS)  positions (stable argsort of ~target)
//   [3BS, 3BS+B)   counts
//
// R14: R13 structure (persistent CTAs, double-buffered smem, 2 barriers/batch,
// flush burst overlapped with next batch's prologue) with the alignment bug
// fixed: posSh is __align__(16) so the float4 LDS.128 reads are legal.

#define Hd 64
#define Wd 64
#define Sd 4096
#define NB 4
#define GRID 912   /* 152 SMs x 6 CTAs (~34KB smem each) */

__global__ __launch_bounds__(256) void bmg_kernel(
    const float* __restrict__ scales,
    const float* __restrict__ rtops,
    const float* __restrict__ rlefts,
    float* __restrict__ out, int B)
{
    const int t = threadIdx.x;
    const int lane = t & 31;

    // big, strictly-aligned arrays first
    __shared__ __align__(16) float posSh[2][Sd];            // 2 x 16 KB
    __shared__ __align__(16) unsigned long long roww[2][64];
    __shared__ int pre[2][64];
    __shared__ int total[2];
    __shared__ int sTop[NB], sBh[NB], sLeft[NB], sBw[NB];   // warp0-private

    const long long BS = (long long)B * Sd;

    int it = 0;
    for (int b = blockIdx.x; b < B; b += GRID, it ^= 1) {

        // ======== warp 0: params + row words + 64-row scan (overlaps the
        //          other warps' flush of the previous iteration) ========
        if (t < 32) {
            if (lane < NB) {
                int idx = b * NB + lane;
                // exact float32 semantics vs the jax reference
                float s = __fadd_rn(0.15f, __fmul_rn(scales[idx], 0.05f));
                int area = (int)(s * 4096.0f);          // pow2 scale: exact
                int bh = (int)sqrt((double)area);       // immune to sqrt.approx
                bh = min(max(bh, 1), Hd);
                int bw = (int)__fdiv_rn((float)area, (float)bh);
                bw = min(max(bw, 1), Wd);
                int maxT = max(Hd - bh + 1, 1);
                int maxL = max(Wd - bw + 1, 1);
                sTop[lane]  = (int)__fmul_rn(rtops[idx],  (float)maxT);
                sLeft[lane] = (int)__fmul_rn(rlefts[idx], (float)maxL);
                sBh[lane] = bh;
                sBw[lane] = bw;
            }
            __syncwarp();

            // lane handles rows `lane` and `lane+32`
            unsigned long long w0 = 0ull, w1 = 0ull;
            #pragma unroll
            for (int k = 0; k < NB; k++) {
                int top = sTop[k], bh = sBh[k], bw = sBw[k];
                unsigned long long m = (bw >= 64) ? ~0ull
                                                  : (((1ull << bw) - 1ull) << sLeft[k]);
                if (lane >= top && lane < top + bh)           w0 |= m;
                if (lane + 32 >= top && lane + 32 < top + bh) w1 |= m;
            }
            roww[it][lane]      = w0;
            roww[it][lane + 32] = w1;
            int c0 = __popcll(w0), c1 = __popcll(w1);

            // two inclusive warp scans -> exclusive prefix over 64 rows
            int s0 = c0, s1 = c1;
            #pragma unroll
            for (int off = 1; off < 32; off <<= 1) {
                int v0 = __shfl_up_sync(0xffffffffu, s0, off);
                int v1 = __shfl_up_sync(0xffffffffu, s1, off);
                if (lane >= off) { s0 += v0; s1 += v1; }
            }
            int tot0 = __shfl_sync(0xffffffffu, s0, 31);
            int tot1 = __shfl_sync(0xffffffffu, s1, 31);
            pre[it][lane]      = s0 - c0;
            pre[it][lane + 32] = tot0 + s1 - c1;
            if (lane == 0) {
                total[it] = tot0 + tot1;
                __stcs(out + 3 * BS + b, (float)(tot0 + tot1));
            }
        }
        __syncthreads();   // buffer[it] (roww/pre/total) ready

        // ======== scatter: stable partition into posSh[it] ========
        // True indices ascending occupy [0,total), False ascending after.
        {
            const int r  = t >> 2;
            const int cb = (t & 3) * 16;
            const unsigned long long rw = roww[it][r];
            unsigned long long beforeMask =
                (cb == 0) ? 0ull : (rw & ((1ull << cb) - 1ull));
            int tOff = pre[it][r] + __popcll(beforeMask);
            int fOff = total[it] + (r * 64 + cb) - tOff;
            float* __restrict__ ps = posSh[it];
            #pragma unroll
            for (int c = 0; c < 16; c++) {
                int idx = r * 64 + cb + c;
                if ((rw >> (cb + c)) & 1ull) ps[tOff++] = (float)idx;
                else                         ps[fOff++] = (float)idx;
            }
        }
        __syncthreads();   // posSh[it] ready

        // ======== flush: one big back-to-back store burst (R11 structure).
        //          Drains while the NEXT iteration computes into buffer it^1. ====
        {
            const long long base = (long long)b * Sd;
            float* __restrict__ ctx = out + base;
            float* __restrict__ tgt = out + BS + base;
            float* __restrict__ pos = out + 2 * BS + base;
            #pragma unroll
            for (int p = 0; p < 4; p++) {
                const int e = p * 1024 + t * 4;
                __stcs(reinterpret_cast<float4*>(pos + e),
                       *reinterpret_cast<const float4*>(posSh[it] + e));
                const unsigned long long rw = roww[it][e >> 6];
                const int cb = e & 63;
                float b0 = (float)((rw >> (cb    )) & 1ull);
                float b1 = (float)((rw >> (cb + 1)) & 1ull);
                float b2 = (float)((rw >> (cb + 2)) & 1ull);
                float b3 = (float)((rw >> (cb + 3)) & 1ull);
                __stcs(reinterpret_cast<float4*>(tgt + e),
                       make_float4(b0, b1, b2, b3));
                __stcs(reinterpret_cast<float4*>(ctx + e),
                       make_float4(1.0f - b0, 1.0f - b1, 1.0f - b2, 1.0f - b3));
            }
        }
        // no trailing barrier needed: next iteration's warp-0 writes target
        // buffer it^1, whose last readers were two barriers ago.
    }
}

extern "C" void kernel_launch(void* const* d_in, const int* in_sizes, int n_in,
                              void* d_out, int out_size) {
    const float* scales = (const float*)d_in[0];
    const float* rtops  = (const float*)d_in[1];
    const float* rlefts = (const float*)d_in[2];
    int B = in_sizes[0] / NB;   // 32768 / 4 = 8192

    float* out = (float*)d_out;
    int grid = (B < GRID) ? B : GRID;
    bmg_kernel<<<grid, 256>>>(scales, rtops, rlefts, out, B);
}

// round 16
// speedup vs baseline: 1.3995x; 1.3995x over previous
#include <cuda_runtime.h>
#include <cuda_bf16.h>

// BlockMaskGenerator: B=8192 batches, NUM_BLOCKS=4 rectangles each, 64x64 grid.
// Output buffer is FLOAT32, flattened in reference order:
//   [0,       BS)  context_mask (= !target)       BS = B*4096
//   [BS,     2BS)  target_mask
//   [2BS,    3BS)  positions (stable argsort of ~target)
//   [3BS, 3BS+B)   counts
//
// R15 = R11 (74us winner) with the flush ALU stripped: mask values are built
// as integer bit patterns (bit * 0x3F800000, ctx via XOR) -> no I2F/FADD and
// no 64-bit shifts in the hot loop. One CTA per batch, monolithic store burst.

#define Hd 64
#define Wd 64
#define Sd 4096
#define NB 4
#define ONEF 0x3F800000u   /* float 1.0f bit pattern */

__global__ __launch_bounds__(256) void bmg_kernel(
    const float* __restrict__ scales,
    const float* __restrict__ rtops,
    const float* __restrict__ rlefts,
    float* __restrict__ out, int B)
{
    const int b = blockIdx.x;
    const int t = threadIdx.x;

    __shared__ __align__(16) float posSh[Sd];    // 16 KB staging for positions
    __shared__ __align__(8) unsigned long long roww[64];
    __shared__ int pre[64];
    __shared__ int sTop[NB], sBh[NB], sLeft[NB], sBw[NB];
    __shared__ int warp0tot, sTotal;

    // ---- rectangle parameters (exact float32 semantics vs the jax reference) ----
    if (t < NB) {
        int idx = b * NB + t;
        float s = __fadd_rn(0.15f, __fmul_rn(scales[idx], 0.05f));
        int area = (int)(s * 4096.0f);                 // power-of-two scale: exact
        int bh = (int)sqrt((double)area);              // immune to sqrt.approx
        bh = min(max(bh, 1), Hd);
        int bw = (int)__fdiv_rn((float)area, (float)bh);
        bw = min(max(bw, 1), Wd);
        int maxT = max(Hd - bh + 1, 1);
        int maxL = max(Wd - bw + 1, 1);
        sTop[t]  = (int)__fmul_rn(rtops[idx],  (float)maxT);
        sLeft[t] = (int)__fmul_rn(rlefts[idx], (float)maxL);
        sBh[t] = bh;
        sBw[t] = bw;
    }
    __syncthreads();

    // ---- build 64-bit row words (bit c of roww[r] = target at (r,c)) ----
    unsigned long long w = 0ull;
    int cnt = 0;
    if (t < 64) {
        #pragma unroll
        for (int k = 0; k < NB; k++) {
            if (t >= sTop[k] && t < sTop[k] + sBh[k]) {
                int bw = sBw[k];
                unsigned long long m = (bw >= 64) ? ~0ull
                                                  : (((1ull << bw) - 1ull) << sLeft[k]);
                w |= m;
            }
        }
        roww[t] = w;
        cnt = __popcll(w);
    }

    // ---- exclusive prefix sum of per-row popcounts (2 warp scans) ----
    int inc = cnt;
    #pragma unroll
    for (int off = 1; off < 32; off <<= 1) {
        int v = __shfl_up_sync(0xffffffffu, inc, off);
        if ((t & 31) >= off) inc += v;
    }
    if (t == 31) warp0tot = inc;
    __syncthreads();
    if (t < 64) {
        int excl = inc - cnt + ((t >= 32) ? warp0tot : 0);
        pre[t] = excl;
        if (t == 63) sTotal = excl + cnt;
    }
    __syncthreads();

    // ---- positions: stable partition scattered into SMEM.
    //      True idx asc occupy [0,total), False idx asc occupy [total,4096). ----
    {
        const int r  = t >> 2;
        const int cb = (t & 3) * 16;
        const unsigned long long rw = roww[r];
        unsigned long long beforeMask = (cb == 0) ? 0ull : (rw & ((1ull << cb) - 1ull));
        int tOff = pre[r] + __popcll(beforeMask);          // true-stream cursor
        int fOff = sTotal + (r * 64 + cb) - tOff;          // false-stream cursor
        #pragma unroll
        for (int c = 0; c < 16; c++) {
            int idx = r * 64 + cb + c;
            if ((rw >> (cb + c)) & 1ull) posSh[tOff++] = (float)idx;
            else                         posSh[fOff++] = (float)idx;
        }
    }
    __syncthreads();

    const long long BS = (long long)B * Sd;
    const long long base = (long long)b * Sd;
    float* __restrict__ ctx = out + base;
    float* __restrict__ tgt = out + BS + base;
    float* __restrict__ pos = out + 2 * BS + base;

    // ---- flush: monolithic store burst, lane-contiguous float4/uint4,
    //      streaming hint. Mask values built with pure int ALU:
    //      bit*0x3F800000 == float 1.0f/0.0f; ctx = tgt ^ 0x3F800000. ----
    const unsigned int* __restrict__ roww32 =
        reinterpret_cast<const unsigned int*>(roww);
    const int wsub = t >> 3;          // which 32-bit word within a 32-word page
    const int sh   = (t & 7) * 4;     // nibble position inside that word
    #pragma unroll
    for (int p = 0; p < 4; p++) {
        const int e = p * 1024 + t * 4;
        // positions flush
        __stcs(reinterpret_cast<float4*>(pos + e),
               *reinterpret_cast<const float4*>(posSh + e));
        // mask nibble -> 4 float-bit-pattern words
        unsigned int word = roww32[p * 32 + wsub];
        unsigned int nib  = (word >> sh);
        unsigned int t0 = (nib        & 1u) * ONEF;
        unsigned int t1 = ((nib >> 1) & 1u) * ONEF;
        unsigned int t2 = ((nib >> 2) & 1u) * ONEF;
        unsigned int t3 = ((nib >> 3) & 1u) * ONEF;
        __stcs(reinterpret_cast<uint4*>(tgt + e), make_uint4(t0, t1, t2, t3));
        __stcs(reinterpret_cast<uint4*>(ctx + e),
               make_uint4(t0 ^ ONEF, t1 ^ ONEF, t2 ^ ONEF, t3 ^ ONEF));
    }

    if (t == 0) __stcs(out + 3 * BS + b, (float)sTotal);
}

extern "C" void kernel_launch(void* const* d_in, const int* in_sizes, int n_in,
                              void* d_out, int out_size) {
    const float* scales = (const float*)d_in[0];
    const float* rtops  = (const float*)d_in[1];
    const float* rlefts = (const float*)d_in[2];
    int B = in_sizes[0] / NB;   // 32768 / 4 = 8192

    float* out = (float*)d_out;
    bmg_kernel<<<B, 256>>>(scales, rtops, rlefts, out, B);
}

// round 17
// speedup vs baseline: 1.5864x; 1.1335x over previous
#include <cuda_runtime.h>
#include <cuda_bf16.h>

// BlockMaskGenerator: B=8192 batches, NUM_BLOCKS=4 rectangles each, 64x64 grid.
// Output buffer is FLOAT32, flattened in reference order:
//   [0,       BS)  context_mask (= !target)       BS = B*4096
//   [BS,     2BS)  target_mask
//   [2BS,    3BS)  positions (stable argsort of ~target)
//   [3BS, 3BS+B)   counts
//
// R16 = R15 (67.4us) with:
//  - positions staged as u16 (halves SMEM round-trip traffic in L1),
//    converted to float at flush via 0x4B000000-bias trick (LOP3+FADD)
//  - whole prologue (params + row words + 64-row scan) inside warp 0:
//    4 __syncthreads -> 2
//  - FP64 sqrt replaced by __fsqrt_rn + exact integer fixup

#define Hd 64
#define Wd 64
#define Sd 4096
#define NB 4
#define ONEF  0x3F800000u   /* float 1.0f bits */
#define BIASI 0x4B000000u   /* float 8388608.0f bits (2^23) */
#define BIASF 8388608.0f

__global__ __launch_bounds__(256) void bmg_kernel(
    const float* __restrict__ scales,
    const float* __restrict__ rtops,
    const float* __restrict__ rlefts,
    float* __restrict__ out, int B)
{
    const int b = blockIdx.x;
    const int t = threadIdx.x;
    const int lane = t & 31;

    __shared__ __align__(16) unsigned short posSh[Sd];     // 8 KB staging
    __shared__ __align__(16) unsigned long long roww[64];
    __shared__ int pre[64];
    __shared__ int sTotal;

    const long long BS = (long long)B * Sd;

    // ======== warp-0 prologue: params + row words + scan (no barriers) ========
    if (t < 32) {
        unsigned int packed = 0;
        if (lane < NB) {
            int idx = b * NB + lane;
            // exact float32 semantics vs the jax reference
            float s = __fadd_rn(0.15f, __fmul_rn(scales[idx], 0.05f));
            int area = (int)(s * 4096.0f);          // pow2 scale: exact
            // floor(sqrt(area)) exactly: correctly-rounded f32 sqrt + fixup
            int bh = (int)__fsqrt_rn((float)area);
            if (bh * bh > area) bh--;
            if ((bh + 1) * (bh + 1) <= area) bh++;
            bh = min(max(bh, 1), Hd);
            int bw = (int)__fdiv_rn((float)area, (float)bh);
            bw = min(max(bw, 1), Wd);
            int maxT = max(Hd - bh + 1, 1);
            int maxL = max(Wd - bw + 1, 1);
            int top  = (int)__fmul_rn(rtops[idx],  (float)maxT);
            int left = (int)__fmul_rn(rlefts[idx], (float)maxL);
            packed = (unsigned)top | ((unsigned)bh << 8)
                   | ((unsigned)left << 16) | ((unsigned)bw << 24);
        }

        // lane handles rows `lane` and `lane+32`
        unsigned long long w0 = 0ull, w1 = 0ull;
        #pragma unroll
        for (int k = 0; k < NB; k++) {
            unsigned int pk = __shfl_sync(0xffffffffu, packed, k);
            int top  =  pk        & 0xFF;
            int bh   = (pk >> 8)  & 0xFF;
            int left = (pk >> 16) & 0xFF;
            int bw   =  pk >> 24;
            unsigned long long m = (bw >= 64) ? ~0ull
                                              : (((1ull << bw) - 1ull) << left);
            if (lane >= top && lane < top + bh)           w0 |= m;
            if (lane + 32 >= top && lane + 32 < top + bh) w1 |= m;
        }
        roww[lane]      = w0;
        roww[lane + 32] = w1;
        int c0 = __popcll(w0), c1 = __popcll(w1);

        // two interleaved inclusive warp scans -> exclusive prefix over 64 rows
        int s0 = c0, s1 = c1;
        #pragma unroll
        for (int off = 1; off < 32; off <<= 1) {
            int v0 = __shfl_up_sync(0xffffffffu, s0, off);
            int v1 = __shfl_up_sync(0xffffffffu, s1, off);
            if (lane >= off) { s0 += v0; s1 += v1; }
        }
        int tot0 = __shfl_sync(0xffffffffu, s0, 31);
        int tot1 = __shfl_sync(0xffffffffu, s1, 31);
        pre[lane]      = s0 - c0;
        pre[lane + 32] = tot0 + s1 - c1;
        if (lane == 0) {
            sTotal = tot0 + tot1;
            __stcs(out + 3 * BS + b, (float)(tot0 + tot1));
        }
    }
    __syncthreads();   // roww/pre/sTotal ready

    // ======== scatter: stable partition into posSh (u16).
    //          True idx asc occupy [0,total), False idx asc after. ========
    {
        const int r  = t >> 2;
        const int cb = (t & 3) * 16;
        const unsigned long long rw = roww[r];
        unsigned long long beforeMask =
            (cb == 0) ? 0ull : (rw & ((1ull << cb) - 1ull));
        int tOff = pre[r] + __popcll(beforeMask);          // true-stream cursor
        int fOff = sTotal + (r * 64 + cb) - tOff;          // false-stream cursor
        #pragma unroll
        for (int c = 0; c < 16; c++) {
            int idx = r * 64 + cb + c;
            if ((rw >> (cb + c)) & 1ull) posSh[tOff++] = (unsigned short)idx;
            else                         posSh[fOff++] = (unsigned short)idx;
        }
    }
    __syncthreads();   // posSh ready

    // ======== flush: monolithic store burst, lane-contiguous 128-bit,
    //          streaming hint. Mask values from int bit patterns. ========
    const long long base = (long long)b * Sd;
    float* __restrict__ ctx = out + base;
    float* __restrict__ tgt = out + BS + base;
    float* __restrict__ pos = out + 2 * BS + base;

    const unsigned int* __restrict__ roww32 =
        reinterpret_cast<const unsigned int*>(roww);
    const int wsub = t >> 3;          // 32-bit word within a 32-word page
    const int sh   = (t & 7) * 4;     // nibble position inside that word
    #pragma unroll
    for (int p = 0; p < 4; p++) {
        const int e = p * 1024 + t * 4;
        // positions: u16 -> float via exponent-bias trick (exact for x < 2^23)
        ushort4 us = *reinterpret_cast<const ushort4*>(posSh + e);
        float4 pf;
        pf.x = __uint_as_float(BIASI | (unsigned)us.x) - BIASF;
        pf.y = __uint_as_float(BIASI | (unsigned)us.y) - BIASF;
        pf.z = __uint_as_float(BIASI | (unsigned)us.z) - BIASF;
        pf.w = __uint_as_float(BIASI | (unsigned)us.w) - BIASF;
        __stcs(reinterpret_cast<float4*>(pos + e), pf);
        // masks: nibble -> 4 float-bit-pattern words; ctx = tgt ^ 1.0f-bits
        unsigned int word = roww32[p * 32 + wsub];
        unsigned int nib  = (word >> sh);
        unsigned int t0 = (nib        & 1u) * ONEF;
        unsigned int t1 = ((nib >> 1) & 1u) * ONEF;
        unsigned int t2 = ((nib >> 2) & 1u) * ONEF;
        unsigned int t3 = ((nib >> 3) & 1u) * ONEF;
        __stcs(reinterpret_cast<uint4*>(tgt + e), make_uint4(t0, t1, t2, t3));
        __stcs(reinterpret_cast<uint4*>(ctx + e),
               make_uint4(t0 ^ ONEF, t1 ^ ONEF, t2 ^ ONEF, t3 ^ ONEF));
    }
}

extern "C" void kernel_launch(void* const* d_in, const int* in_sizes, int n_in,
                              void* d_out, int out_size) {
    const float* scales = (const float*)d_in[0];
    const float* rtops  = (const float*)d_in[1];
    const float* rlefts = (const float*)d_in[2];
    int B = in_sizes[0] / NB;   // 32768 / 4 = 8192

    float* out = (float*)d_out;
    bmg_kernel<<<B, 256>>>(scales, rtops, rlefts, out, B);
}